// round 9
// baseline (speedup 1.0000x reference)
#include <cuda_runtime.h>
#include <cuda_bf16.h>
#include <cstdint>

#define N_EMBED 384
#define NUM_EXPERTS 8
#define THREADS 128
#define TPT 2
#define TOK_PER_BLK (THREADS * TPT)   // 256
#define KC 32
#define PITCH 36                      // conflict-free .128 phases (stride 144B)
#define NCHUNK (N_EMBED / KC)         // 12

#define XS_BUF_FLOATS (TOK_PER_BLK * PITCH)       // 9216 floats = 36864 B
#define SMEM_TOTAL (2 * XS_BUF_FLOATS * 4)        // 73728 B -> 3 CTAs/SM

#define NW2 (NUM_EXPERTS * N_EMBED / 2)           // 1536 ulonglong2 weight pairs

typedef unsigned long long ull;

// constant-space weights: cw[i] covers flat dims {2i, 2i+1} of [e][d] (each ull = packed (wr,wn))
__constant__ ulonglong2 cw[NW2];
__constant__ ull cbias[NUM_EXPERTS];              // packed (b_route[e], b_noise[e])

__device__ ulonglong2 g_scratch[NW2 + 4];

__device__ __forceinline__ void ffma2(ull& a, ull b, ull c) {
    asm("fma.rn.f32x2 %0, %1, %2, %0;" : "+l"(a) : "l"(b), "l"(c));
}
__device__ __forceinline__ ull bcast2(float v) {
    ull r; asm("mov.b64 %0, {%1, %1};" : "=l"(r) : "f"(v)); return r;
}
__device__ __forceinline__ ull pack2(float lo, float hi) {
    ull r; asm("mov.b64 %0, {%1, %2};" : "=l"(r) : "f"(lo), "f"(hi)); return r;
}
__device__ __forceinline__ void unpack2(ull a, float& lo, float& hi) {
    asm("mov.b64 {%0, %1}, %2;" : "=f"(lo), "=f"(hi) : "l"(a));
}
__device__ __forceinline__ uint32_t smem_u32(const void* p) {
    return (uint32_t)__cvta_generic_to_shared(p);
}
__device__ __forceinline__ void cp16(uint32_t dst, const void* src, int pred) {
    asm volatile(
        "{ .reg .pred q; setp.ne.b32 q, %2, 0;\n\t"
        "@q cp.async.ca.shared.global [%0], [%1], 16; }"
        :: "r"(dst), "l"(src), "r"(pred));
}

__global__ void repack_kernel(const float* __restrict__ wr, const float* __restrict__ wn,
                              const float* __restrict__ br, const float* __restrict__ bn) {
    int i = blockIdx.x * blockDim.x + threadIdx.x;
    if (i < NW2) {
        g_scratch[i] = make_ulonglong2(pack2(wr[2 * i],     wn[2 * i]),
                                       pack2(wr[2 * i + 1], wn[2 * i + 1]));
    } else if (i < NW2 + 4) {
        int j = i - NW2;   // experts 2j, 2j+1
        g_scratch[i] = make_ulonglong2(pack2(br[2 * j],     bn[2 * j]),
                                       pack2(br[2 * j + 1], bn[2 * j + 1]));
    }
}

__global__ __launch_bounds__(THREADS, 3)
void noisy_topk_router_kernel(
    const float* __restrict__ x,        // [n_tok, 384]
    const float* __restrict__ noise,    // [n_tok, 8]
    float* __restrict__ out,
    int n_tok, int write_idx)
{
    extern __shared__ char smem[];
    float* xs = reinterpret_cast<float*>(smem);   // [2][256*36]

    const int tid = threadIdx.x;
    const int t0  = blockIdx.x * TOK_PER_BLK;

    // ---- async staging of x chunks (16 float4 per thread per chunk) ----
    auto stage = [&](int c) {
        float* dst = xs + (c & 1) * XS_BUF_FLOATS;
#pragma unroll
        for (int r = 0; r < TOK_PER_BLK * (KC / 4) / THREADS; r++) {   // 16
            int idx = tid + r * THREADS;
            int tok = idx >> 3, q = idx & 7;
            const float* src = x + (size_t)(t0 + tok) * N_EMBED + c * KC + q * 4;
            cp16(smem_u32(dst + tok * PITCH + q * 4), src, (t0 + tok < n_tok) ? 1 : 0);
        }
        asm volatile("cp.async.commit_group;" ::: "memory");
    };

    stage(0);
    stage(1);

    // prefetch noise for this thread's 2 tokens while cp.asyncs fly
    float4 nzr[TPT][2];
#pragma unroll
    for (int k = 0; k < TPT; k++) {
        int t = t0 + tid + k * THREADS;
        if (t < n_tok) {
            const float4* np = reinterpret_cast<const float4*>(noise + (size_t)t * NUM_EXPERTS);
            nzr[k][0] = np[0]; nzr[k][1] = np[1];
        } else {
            nzr[k][0] = nzr[k][1] = make_float4(0.f, 0.f, 0.f, 0.f);
        }
    }

    asm volatile("cp.async.wait_group 1;" ::: "memory");   // chunk 0 landed
    __syncthreads();

    ull acc[TPT][NUM_EXPERTS];
#pragma unroll
    for (int k = 0; k < TPT; k++)
#pragma unroll
        for (int e = 0; e < NUM_EXPERTS; e++)
            acc[k][e] = cbias[e];                          // biases pre-packed (br, bn)

    for (int c = 0; c < NCHUNK; c++) {
        const float* buf = xs + (c & 1) * XS_BUF_FLOATS;
#pragma unroll
        for (int j = 0; j < KC; j += 4) {
            ull xb[TPT][4];
#pragma unroll
            for (int k = 0; k < TPT; k++) {
                float4 xv = *reinterpret_cast<const float4*>(&buf[(tid + k * THREADS) * PITCH + j]);
                xb[k][0] = bcast2(xv.x); xb[k][1] = bcast2(xv.y);
                xb[k][2] = bcast2(xv.z); xb[k][3] = bcast2(xv.w);
            }
            const int base = (c * KC + j) >> 1;            // ulonglong2 index within expert row
#pragma unroll
            for (int e = 0; e < NUM_EXPERTS; e++) {
                ulonglong2 wa = cw[e * (N_EMBED / 2) + base];        // dims d, d+1
                ulonglong2 wb = cw[e * (N_EMBED / 2) + base + 1];    // dims d+2, d+3
#pragma unroll
                for (int k = 0; k < TPT; k++) {
                    ffma2(acc[k][e], xb[k][0], wa.x);
                    ffma2(acc[k][e], xb[k][1], wa.y);
                    ffma2(acc[k][e], xb[k][2], wb.x);
                    ffma2(acc[k][e], xb[k][3], wb.y);
                }
            }
        }
        __syncthreads();   // readers of buf (c&1) done
        if (c + 2 < NCHUNK) stage(c + 2);
        else asm volatile("cp.async.commit_group;" ::: "memory");
        asm volatile("cp.async.wait_group 1;" ::: "memory");   // chunk c+1 landed
        __syncthreads();
    }

    // ---- epilogue per token ----
#pragma unroll
    for (int k = 0; k < TPT; k++) {
        int t = t0 + tid + k * THREADS;
        if (t >= n_tok) continue;

        float nz[NUM_EXPERTS] = {nzr[k][0].x, nzr[k][0].y, nzr[k][0].z, nzr[k][0].w,
                                 nzr[k][1].x, nzr[k][1].y, nzr[k][1].z, nzr[k][1].w};

        float v[NUM_EXPERTS];
#pragma unroll
        for (int e = 0; e < NUM_EXPERTS; e++) {
            float lg, nl;
            unpack2(acc[k][e], lg, nl);
            // jax.nn.softplus: max(x,0) + log1p(exp(-|x|))
            float sp = fmaxf(nl, 0.0f) + log1pf(expf(-fabsf(nl)));
            v[e] = lg + nz[e] * sp;
        }

        // top-2, first-occurrence tie-break (matches jax.lax.top_k)
        float v0 = v[0]; int i0 = 0;
#pragma unroll
        for (int e = 1; e < NUM_EXPERTS; e++)
            if (v[e] > v0) { v0 = v[e]; i0 = e; }
        float v1 = -3.402823466e+38f; int i1 = 0;
#pragma unroll
        for (int e = 0; e < NUM_EXPERTS; e++) {
            bool take = (e != i0) && (v[e] > v1);
            if (take) { v1 = v[e]; i1 = e; }
        }

        float e1 = expf(v1 - v0);
        float inv = 1.0f / (1.0f + e1);
        float p0 = inv, p1 = e1 * inv;

        float o[NUM_EXPERTS];
#pragma unroll
        for (int e = 0; e < NUM_EXPERTS; e++)
            o[e] = (e == i0) ? p0 : ((e == i1) ? p1 : 0.0f);

        float4* op = reinterpret_cast<float4*>(out + (size_t)t * NUM_EXPERTS);
        op[0] = make_float4(o[0], o[1], o[2], o[3]);
        op[1] = make_float4(o[4], o[5], o[6], o[7]);

        if (write_idx) {
            float2* ip = reinterpret_cast<float2*>(out + (size_t)n_tok * NUM_EXPERTS);
            ip[t] = make_float2((float)i0, (float)i1);
        }
    }
}

extern "C" void kernel_launch(void* const* d_in, const int* in_sizes, int n_in,
                              void* d_out, int out_size) {
    const float* x       = (const float*)d_in[0];
    const float* noise   = (const float*)d_in[1];
    const float* w_route = (const float*)d_in[2];
    const float* b_route = (const float*)d_in[3];
    const float* w_noise = (const float*)d_in[4];
    const float* b_noise = (const float*)d_in[5];
    float* out = (float*)d_out;

    int n_tok = in_sizes[0] / N_EMBED;
    int write_idx = (out_size >= n_tok * NUM_EXPERTS + n_tok * 2) ? 1 : 0;

    // 1) interleave weights+biases into device scratch
    repack_kernel<<<(NW2 + 4 + 255) / 256, 256>>>(w_route, w_noise, b_route, b_noise);

    // 2) D2D copies into constant space (graph-capturable memcpy nodes)
    void* scratch_ptr = nullptr;
    cudaGetSymbolAddress(&scratch_ptr, g_scratch);
    cudaMemcpyToSymbolAsync(cw, scratch_ptr, NW2 * sizeof(ulonglong2), 0,
                            cudaMemcpyDeviceToDevice, 0);
    cudaMemcpyToSymbolAsync(cbias, (char*)scratch_ptr + NW2 * sizeof(ulonglong2),
                            NUM_EXPERTS * sizeof(ull), 0,
                            cudaMemcpyDeviceToDevice, 0);

    // 3) main kernel
    cudaFuncSetAttribute(noisy_topk_router_kernel,
                         cudaFuncAttributeMaxDynamicSharedMemorySize, SMEM_TOTAL);
    int grid = (n_tok + TOK_PER_BLK - 1) / TOK_PER_BLK;   // 256
    noisy_topk_router_kernel<<<grid, THREADS, SMEM_TOTAL>>>(
        x, noise, out, n_tok, write_idx);
}

// round 10
// speedup vs baseline: 2.9747x; 2.9747x over previous
#include <cuda_runtime.h>
#include <cuda_bf16.h>
#include <cstdint>

#define N_EMBED 384
#define NUM_EXPERTS 8
#define THREADS 64            // 2 warps per CTA
#define TOK_PER_WARP 64       // lanes hold tokens lid and lid+32
#define TOK_PER_BLK 128
#define KC 16                 // dims per chunk
#define NCHUNK 24
#define NBUF 3                // per-warp cp.async ring depth
#define PITCH 20              // floats per token row, conflict-free .128 phases

#define WS_BYTES (NUM_EXPERTS * N_EMBED * 8)   // 24576
#define SB_OFF   WS_BYTES                       // 16 bias floats
#define XS_OFF   (WS_BYTES + 64)                // 24640
#define BUF_FLOATS (TOK_PER_WARP * PITCH)       // 1280 floats = 5120 B
#define SMEM_TOTAL (XS_OFF + 2 * NBUF * BUF_FLOATS * 4)   // 55360 B -> 4 CTAs/SM

typedef unsigned long long ull;

__device__ __forceinline__ void ffma2(ull& a, ull b, ull c) {
    asm("fma.rn.f32x2 %0, %1, %2, %0;" : "+l"(a) : "l"(b), "l"(c));
}
__device__ __forceinline__ ull bcast2(float v) {
    ull r; asm("mov.b64 %0, {%1, %1};" : "=l"(r) : "f"(v)); return r;
}
__device__ __forceinline__ ull pack2(float lo, float hi) {
    ull r; asm("mov.b64 %0, {%1, %2};" : "=l"(r) : "f"(lo), "f"(hi)); return r;
}
__device__ __forceinline__ void unpack2(ull a, float& lo, float& hi) {
    asm("mov.b64 {%0, %1}, %2;" : "=f"(lo), "=f"(hi) : "l"(a));
}
__device__ __forceinline__ uint32_t smem_u32(const void* p) {
    return (uint32_t)__cvta_generic_to_shared(p);
}
__device__ __forceinline__ void cp16(uint32_t dst, const void* src, int pred) {
    asm volatile(
        "{ .reg .pred q; setp.ne.b32 q, %2, 0;\n\t"
        "@q cp.async.ca.shared.global [%0], [%1], 16; }"
        :: "r"(dst), "l"(src), "r"(pred));
}

__global__ __launch_bounds__(THREADS)
void noisy_topk_router_kernel(
    const float* __restrict__ x,        // [n_tok, 384]
    const float* __restrict__ noise,    // [n_tok, 8]
    const float* __restrict__ w_route,  // [8, 384]
    const float* __restrict__ b_route,  // [8]
    const float* __restrict__ w_noise,  // [8, 384]
    const float* __restrict__ b_noise,  // [8]
    float* __restrict__ out,
    int n_tok, int write_idx)
{
    extern __shared__ char smem[];
    float2* ws = reinterpret_cast<float2*>(smem);                // (route, noise) per [e][d]
    float*  sb = reinterpret_cast<float*>(smem + SB_OFF);        // 16 biases
    float*  xs = reinterpret_cast<float*>(smem + XS_OFF);        // per-warp ring buffers

    const int tid  = threadIdx.x;
    const int w    = tid >> 5;
    const int lane = tid & 31;
    const int t0   = blockIdx.x * TOK_PER_BLK;
    const int tw0  = t0 + w * TOK_PER_WARP;    // this warp's first token

    float* mybuf = xs + w * NBUF * BUF_FLOATS;

    // ---- per-warp staging of its OWN 64 tokens, chunk c (16 dims) ----
    auto stage = [&](int c) {
        float* dst = mybuf + (c % NBUF) * BUF_FLOATS;
#pragma unroll
        for (int r = 0; r < 8; r++) {                 // 64 tok * 4 float4 / 32 lanes
            int idx = lane + r * 32;
            int tok = idx >> 2, q = idx & 3;
            const float* src = x + (size_t)(tw0 + tok) * N_EMBED + c * KC + q * 4;
            cp16(smem_u32(dst + tok * PITCH + q * 4), src, (tw0 + tok < n_tok) ? 1 : 0);
        }
        asm volatile("cp.async.commit_group;" ::: "memory");
    };

    // start DRAM traffic immediately (groups 0,1,2)
    stage(0);
    stage(1);
    stage(2);

    // cooperative ws + sb fill (both warps), then the ONLY CTA barrier
    for (int i = tid; i < NUM_EXPERTS * N_EMBED; i += THREADS)
        ws[i] = make_float2(w_route[i], w_noise[i]);
    if (tid < NUM_EXPERTS)           sb[tid] = b_route[tid];
    else if (tid < 2 * NUM_EXPERTS)  sb[tid] = b_noise[tid - NUM_EXPERTS];
    __syncthreads();

    ull acc[2][NUM_EXPERTS];
#pragma unroll
    for (int k = 0; k < 2; k++)
#pragma unroll
        for (int e = 0; e < NUM_EXPERTS; e++)
            acc[k][e] = pack2(sb[e], sb[NUM_EXPERTS + e]);   // fold biases

    const float* wsf = reinterpret_cast<const float*>(ws);

    for (int c = 0; c < NCHUNK; c++) {
        // committed so far: 3 + c groups; wait until <=2 outstanding => group c landed
        asm volatile("cp.async.wait_group 2;" ::: "memory");
        __syncwarp();

        const float* buf = mybuf + (c % NBUF) * BUF_FLOATS;
#pragma unroll
        for (int j = 0; j < KC; j += 4) {
            float4 va = *reinterpret_cast<const float4*>(&buf[lane * PITCH + j]);
            float4 vb = *reinterpret_cast<const float4*>(&buf[(lane + 32) * PITCH + j]);
            ull a0 = bcast2(va.x), a1 = bcast2(va.y), a2 = bcast2(va.z), a3 = bcast2(va.w);
            ull b0 = bcast2(vb.x), b1 = bcast2(vb.y), b2 = bcast2(vb.z), b3 = bcast2(vb.w);
            const int d = c * KC + j;
#pragma unroll
            for (int e = 0; e < NUM_EXPERTS; e++) {
                const float* wpe = wsf + (e * N_EMBED + d) * 2;
                ulonglong2 wa = *reinterpret_cast<const ulonglong2*>(wpe);      // d, d+1
                ulonglong2 wb = *reinterpret_cast<const ulonglong2*>(wpe + 4);  // d+2, d+3
                ffma2(acc[0][e], a0, wa.x);
                ffma2(acc[1][e], b0, wa.x);
                ffma2(acc[0][e], a1, wa.y);
                ffma2(acc[1][e], b1, wa.y);
                ffma2(acc[0][e], a2, wb.x);
                ffma2(acc[1][e], b2, wb.x);
                ffma2(acc[0][e], a3, wb.y);
                ffma2(acc[1][e], b3, wb.y);
            }
        }
        __syncwarp();
        if (c + 3 < NCHUNK) stage(c + 3);   // ring slot (c+3)%NBUF == c%NBUF, readers done
        else asm volatile("cp.async.commit_group;" ::: "memory");  // keep group count exact
    }

    // ---- epilogue: lane handles tokens tw0+lane and tw0+lane+32 ----
#pragma unroll
    for (int k = 0; k < 2; k++) {
        int t = tw0 + lane + k * 32;
        if (t >= n_tok) continue;

        const float4* np = reinterpret_cast<const float4*>(noise + (size_t)t * NUM_EXPERTS);
        float4 nz0 = np[0], nz1 = np[1];
        float nz[NUM_EXPERTS] = {nz0.x, nz0.y, nz0.z, nz0.w, nz1.x, nz1.y, nz1.z, nz1.w};

        float v[NUM_EXPERTS];
#pragma unroll
        for (int e = 0; e < NUM_EXPERTS; e++) {
            float lg, nl;
            unpack2(acc[k][e], lg, nl);
            // jax.nn.softplus: max(x,0) + log1p(exp(-|x|))
            float sp = fmaxf(nl, 0.0f) + log1pf(expf(-fabsf(nl)));
            v[e] = lg + nz[e] * sp;
        }

        // top-2, first-occurrence tie-break (matches jax.lax.top_k)
        float v0 = v[0]; int i0 = 0;
#pragma unroll
        for (int e = 1; e < NUM_EXPERTS; e++)
            if (v[e] > v0) { v0 = v[e]; i0 = e; }
        float v1 = -3.402823466e+38f; int i1 = 0;
#pragma unroll
        for (int e = 0; e < NUM_EXPERTS; e++) {
            bool take = (e != i0) && (v[e] > v1);
            if (take) { v1 = v[e]; i1 = e; }
        }

        float e1 = expf(v1 - v0);
        float inv = 1.0f / (1.0f + e1);
        float p0 = inv, p1 = e1 * inv;

        float o[NUM_EXPERTS];
#pragma unroll
        for (int e = 0; e < NUM_EXPERTS; e++)
            o[e] = (e == i0) ? p0 : ((e == i1) ? p1 : 0.0f);

        float4* op = reinterpret_cast<float4*>(out + (size_t)t * NUM_EXPERTS);
        op[0] = make_float4(o[0], o[1], o[2], o[3]);
        op[1] = make_float4(o[4], o[5], o[6], o[7]);

        if (write_idx) {
            float2* ip = reinterpret_cast<float2*>(out + (size_t)n_tok * NUM_EXPERTS);
            ip[t] = make_float2((float)i0, (float)i1);
        }
    }
}

extern "C" void kernel_launch(void* const* d_in, const int* in_sizes, int n_in,
                              void* d_out, int out_size) {
    const float* x       = (const float*)d_in[0];
    const float* noise   = (const float*)d_in[1];
    const float* w_route = (const float*)d_in[2];
    const float* b_route = (const float*)d_in[3];
    const float* w_noise = (const float*)d_in[4];
    const float* b_noise = (const float*)d_in[5];
    float* out = (float*)d_out;

    int n_tok = in_sizes[0] / N_EMBED;
    int write_idx = (out_size >= n_tok * NUM_EXPERTS + n_tok * 2) ? 1 : 0;

    cudaFuncSetAttribute(noisy_topk_router_kernel,
                         cudaFuncAttributeMaxDynamicSharedMemorySize, SMEM_TOTAL);

    int grid = (n_tok + TOK_PER_BLK - 1) / TOK_PER_BLK;   // 512
    noisy_topk_router_kernel<<<grid, THREADS, SMEM_TOTAL>>>(
        x, noise, w_route, b_route, w_noise, b_noise, out, n_tok, write_idx);
}